// round 12
// baseline (speedup 1.0000x reference)
#include <cuda_runtime.h>
#include <cuda_bf16.h>
#include <cuda_fp16.h>
#include <cstdint>
#include <cstddef>

#define HID   128
#define MAXN  50000
#define MAXE  800000
#define DCAP  96

// ---------------- scratch (device globals: allocation-free rule) ------------
__device__ __align__(16) float  g_A [(size_t)MAXN * HID];  // A = z@Wm_top (fp32)
__device__ __align__(16) __half g_Bh[(size_t)MAXN * HID];  // B = z@Wm_mid (fp16)
__device__ __align__(16) float  g_M [(size_t)MAXN * HID];  // m matrix
__device__ __align__(16) uint2  g_epk[(size_t)MAXN * DCAP]; // bucket: (src, w as half2)
__device__ int g_cnt[MAXN];
// packed B images: [img][hi 16KB | lo 16KB], img = 64-k subchunk (x n-block)
__device__ __align__(1024) unsigned char g_Bm[4 * 32768]; // GEMM1: img = nblk*2 + ksub
__device__ __align__(1024) unsigned char g_Bu[4 * 32768]; // GEMM2: img = ksub (0..3)

// ---------------- helpers ----------------------------------------------------
__device__ __forceinline__ uint32_t s2u(const void* p) {
    uint32_t a;
    asm("{ .reg .u64 t; cvta.to.shared.u64 t, %1; cvt.u32.u64 %0, t; }" : "=r"(a) : "l"(p));
    return a;
}

// byte offset in a 16KB [128 rows][64 bf16] tile, XOR-swizzled at 16B grain
__device__ __forceinline__ uint32_t o64(int row, int kc) {
    return ((uint32_t)row << 7) + (((uint32_t)(kc ^ (row & 7))) << 4);
}

#define LDMX4(r0, r1, r2, r3, a) \
    asm volatile("ldmatrix.sync.aligned.m8n8.x4.shared.b16 {%0,%1,%2,%3}, [%4];" \
        : "=r"(r0), "=r"(r1), "=r"(r2), "=r"(r3) : "r"(a))

#define MMA16816(d, a0, a1, a2, a3, b0, b1) \
    asm volatile("mma.sync.aligned.m16n8k16.row.col.f32.bf16.bf16.f32 " \
        "{%0,%1,%2,%3}, {%4,%5,%6,%7}, {%8,%9}, {%0,%1,%2,%3};" \
        : "+f"((d)[0]), "+f"((d)[1]), "+f"((d)[2]), "+f"((d)[3]) \
        : "r"(a0), "r"(a1), "r"(a2), "r"(a3), "r"(b0), "r"(b1))

#define CPASYNC16(dst, src) \
    asm volatile("cp.async.cg.shared.global [%0], [%1], 16;" :: "r"(dst), "l"(src))

// ---------------- prep: zero counts + pack both B operand images --------------
__global__ void prep(const float* __restrict__ Wm, const float* __restrict__ Wu, int n) {
    int i = blockIdx.x * blockDim.x + threadIdx.x;
    if (i < 32768) {
        { // Bm: img=(n>>7)*2+(k>>6): B[n&127][k&63] = W_eff[k][n]
            int nn = i & 255, k = i >> 8;
            float v = (nn < 128) ? Wm[k * 128 + nn] : Wm[(128 + k) * 128 + (nn - 128)];
            __nv_bfloat16 h = __float2bfloat16(v);
            __nv_bfloat16 l = __float2bfloat16(v - __bfloat162float(h));
            int kk = k & 63;
            uint32_t o = (uint32_t)((nn >> 7) * 2 + (k >> 6)) * 32768
                       + o64(nn & 127, kk >> 3) + (kk & 7) * 2;
            *(__nv_bfloat16*)(g_Bm + o)         = h;
            *(__nv_bfloat16*)(g_Bm + o + 16384) = l;
        }
        { // Bu: img=(k>>6): B[n][k&63] = Wu[k][n]
            int nn = i & 127, k = i >> 7;
            float v = Wu[k * 128 + nn];
            __nv_bfloat16 h = __float2bfloat16(v);
            __nv_bfloat16 l = __float2bfloat16(v - __bfloat162float(h));
            int kk = k & 63;
            uint32_t o = (uint32_t)(k >> 6) * 32768 + o64(nn, kk >> 3) + (kk & 7) * 2;
            *(__nv_bfloat16*)(g_Bu + o)         = h;
            *(__nv_bfloat16*)(g_Bu + o + 16384) = l;
        }
    }
    if (i < n) g_cnt[i] = 0;
}

// ---------------- node_max v3: payload-pipelined, 75% occ ---------------------
//   m[d] = deg ? f32(max2_e(Bh[src_e] + w_e*r_h)) + A[d] + bm : 0
// Software pipeline: payload batch e+4 prefetched (clamped) while batch e's
// B-rows load & compute -> payload latency hidden behind B latency.
__global__ __launch_bounds__(256, 6) void node_max(const float* __restrict__ r,
                                                   const float* __restrict__ bm, int n)
{
    int warp = (blockIdx.x * blockDim.x + threadIdx.x) >> 5;
    int lane = threadIdx.x & 31;
    if (warp >= n) return;
    const int d = warp;
    const int c4 = lane * 4;

    float4 rvf = *(const float4*)&r[c4];
    const __half2 rv0 = __floats2half2_rn(rvf.x, rvf.y);
    const __half2 rv1 = __floats2half2_rn(rvf.z, rvf.w);

    int deg = g_cnt[d];
    if (deg > DCAP) deg = DCAP;
    const uint2* pay = &g_epk[(size_t)d * DCAP];
    const __half* Bbase = g_Bh + c4;

    float4 acc;
    if (deg > 0) {
        const __half2 NEGI = __half2half2(__ushort_as_half(0xFC00));
        __half2 a0 = NEGI, a1 = NEGI;
        const int dm1 = deg - 1;

        uint2 pc[4];
#pragma unroll
        for (int j = 0; j < 4; j++) pc[j] = pay[j < dm1 ? j : dm1];

        for (int e = 0; e < deg; e += 4) {
            const int rem = deg - e;
            // B loads for current batch (independent of prefetch below)
            uint2 b[4];
#pragma unroll
            for (int j = 0; j < 4; j++)
                b[j] = *(const uint2*)(Bbase + (size_t)pc[j].x * HID);
            // prefetch next payload batch (clamped; overlaps B latency)
            uint2 pn[4];
#pragma unroll
            for (int j = 0; j < 4; j++) {
                int idx = e + 4 + j;
                pn[j] = pay[idx < dm1 ? idx : dm1];
            }
            // compute current batch (guard tail)
#pragma unroll
            for (int j = 0; j < 4; j++) {
                if (j < rem) {
                    __half2 ww = *(__half2*)&pc[j].y;
                    a0 = __hmax2(a0, __hfma2(ww, rv0, *(__half2*)&b[j].x));
                    a1 = __hmax2(a1, __hfma2(ww, rv1, *(__half2*)&b[j].y));
                }
            }
#pragma unroll
            for (int j = 0; j < 4; j++) pc[j] = pn[j];
        }
        float2 f0 = __half22float2(a0);
        float2 f1 = __half22float2(a1);
        float4 a   = *(const float4*)&g_A[(size_t)d * HID + c4];
        float4 bmv = *(const float4*)&bm[c4];
        acc = make_float4(f0.x + a.x + bmv.x, f0.y + a.y + bmv.y,
                          f1.x + a.z + bmv.z, f1.y + a.w + bmv.w);
    } else {
        acc = make_float4(0.f, 0.f, 0.f, 0.f);
    }
    *(float4*)&g_M[(size_t)d * HID + c4] = acc;
}

// ---------------- split-bf16 HMMA GEMM + fused edge scatter -------------------
// smem: AH 16K | AL 16K | B0 32K | B1 32K = 96KB (2 CTA/SM)
// y=0 tile -> fp32 C (+bias); y=1 tile (GEMM1 only) -> fp16 Chalf, no bias.
// acc = Ah*Bh + Ah*Bl + Al*Bh  (split-bf16, ~2^-16 rel err)
// If edgesPerBlk > 0: after the epilogue each CTA scatters its edge slice into
// the per-destination buckets (depends only on prep's zeroed counters).
#define SM_AH 0
#define SM_AL 16384
#define SM_B0 32768
#define MG_SMEM 98304

__global__ __launch_bounds__(256, 2) void mma_gemm(
    const float* __restrict__ A0, const float* __restrict__ A1,
    const unsigned char* __restrict__ Bimg, const float* __restrict__ bias,
    float* __restrict__ C, __half* __restrict__ Chalf, int Mrows, int Kchunks,
    const int* __restrict__ esrc, const int* __restrict__ edst,
    const float* __restrict__ ew, int E, int edgesPerBlk)
{
    extern __shared__ __align__(1024) unsigned char sm[];
    const uint32_t sb = s2u(sm);
    const int tid = threadIdx.x, w = tid >> 5, lane = tid & 31;
    const int m0 = blockIdx.x * 128;
    const int totalKsubs = Kchunks * 2;

    float acc[2][8][4];
#pragma unroll
    for (int i = 0; i < 2; i++)
#pragma unroll
        for (int j = 0; j < 8; j++)
#pragma unroll
            for (int q = 0; q < 4; q++) acc[i][j][q] = 0.f;

    const int mw = (w & 3) * 32;      // warp M offset in tile
    const int nw = (w >> 2) * 64;     // warp N offset in tile

    // prefetch B(0) into buffer 0
    {
        const unsigned char* srcB = Bimg +
            (size_t)(blockIdx.y * totalKsubs) * 32768 + tid * 16;
        uint32_t dstB = sb + SM_B0 + tid * 16;
#pragma unroll
        for (int i = 0; i < 8; i++)
            CPASYNC16(dstB + i * 4096, srcB + i * 4096);
        asm volatile("cp.async.commit_group;");
    }

    for (int gk = 0; gk < totalKsubs; ++gk) {
        if (gk) __syncthreads();

        // prefetch B(gk+1) into the other buffer (clamped on last iter)
        {
            int nxt = (gk + 1 < totalKsubs) ? gk + 1 : gk;
            const unsigned char* srcB = Bimg +
                (size_t)(blockIdx.y * totalKsubs + nxt) * 32768 + tid * 16;
            uint32_t dstB = sb + SM_B0 + ((gk + 1) & 1) * 32768 + tid * 16;
#pragma unroll
            for (int i = 0; i < 8; i++)
                CPASYNC16(dstB + i * 4096, srcB + i * 4096);
            asm volatile("cp.async.commit_group;");
        }
        // A: load fp32, split to bf16 hi/lo, store swizzled (overlaps cp.async)
        {
            const float* Ap = (gk >> 1) ? A1 : A0;
            const int kbase = (gk & 1) * 64;
            int r = tid >> 1, kh = (tid & 1) * 32;
            int g = m0 + r;
            const float* rowp = &Ap[(size_t)g * 128 + kbase + kh];
#pragma unroll
            for (int i = 0; i < 8; i++) {
                int k = kh + i * 4;
                float4 v = make_float4(0.f, 0.f, 0.f, 0.f);
                if (g < Mrows) v = *(const float4*)(rowp + i * 4);
                __nv_bfloat16 h0 = __float2bfloat16(v.x);
                __nv_bfloat16 h1 = __float2bfloat16(v.y);
                __nv_bfloat16 h2 = __float2bfloat16(v.z);
                __nv_bfloat16 h3 = __float2bfloat16(v.w);
                __nv_bfloat16 l0 = __float2bfloat16(v.x - __bfloat162float(h0));
                __nv_bfloat16 l1 = __float2bfloat16(v.y - __bfloat162float(h1));
                __nv_bfloat16 l2 = __float2bfloat16(v.z - __bfloat162float(h2));
                __nv_bfloat16 l3 = __float2bfloat16(v.w - __bfloat162float(h3));
                uint32_t o = o64(r, k >> 3) + (k & 7) * 2;
                uint2 ph = make_uint2(
                    ((uint32_t)__bfloat16_as_ushort(h1) << 16) | __bfloat16_as_ushort(h0),
                    ((uint32_t)__bfloat16_as_ushort(h3) << 16) | __bfloat16_as_ushort(h2));
                uint2 pl = make_uint2(
                    ((uint32_t)__bfloat16_as_ushort(l1) << 16) | __bfloat16_as_ushort(l0),
                    ((uint32_t)__bfloat16_as_ushort(l3) << 16) | __bfloat16_as_ushort(l2));
                *(uint2*)(sm + SM_AH + o) = ph;
                *(uint2*)(sm + SM_AL + o) = pl;
            }
        }
        // wait for B(gk) (allow B(gk+1) to remain in flight)
        asm volatile("cp.async.wait_group 1;" ::: "memory");
        __syncthreads();

        const uint32_t sbB = sb + SM_B0 + (gk & 1) * 32768;

        // compute: 4 k16 steps over this 64-k subchunk
#pragma unroll
        for (int ks = 0; ks < 4; ++ks) {
            const int kc = ks * 2;
            uint32_t ah[2][4], al[2][4];
#pragma unroll
            for (int mt = 0; mt < 2; mt++) {
                int row = mw + mt * 16 + (lane & 15);
                uint32_t off = o64(row, kc + (lane >> 4));
                LDMX4(ah[mt][0], ah[mt][1], ah[mt][2], ah[mt][3], sb + SM_AH + off);
                LDMX4(al[mt][0], al[mt][1], al[mt][2], al[mt][3], sb + SM_AL + off);
            }
#pragma unroll
            for (int ng = 0; ng < 4; ng++) {
                int rowb = nw + ng * 16 + (lane & 7) + ((lane >> 4) << 3);
                uint32_t offb = o64(rowb, kc + ((lane >> 3) & 1));
                uint32_t bh0, bh1, bh2, bh3, bl0, bl1, bl2, bl3;
                LDMX4(bh0, bh1, bh2, bh3, sbB + offb);
                LDMX4(bl0, bl1, bl2, bl3, sbB + 16384 + offb);
#pragma unroll
                for (int mt = 0; mt < 2; mt++) {
                    MMA16816(acc[mt][2 * ng],     ah[mt][0], ah[mt][1], ah[mt][2], ah[mt][3], bh0, bh1);
                    MMA16816(acc[mt][2 * ng],     ah[mt][0], ah[mt][1], ah[mt][2], ah[mt][3], bl0, bl1);
                    MMA16816(acc[mt][2 * ng],     al[mt][0], al[mt][1], al[mt][2], al[mt][3], bh0, bh1);
                    MMA16816(acc[mt][2 * ng + 1], ah[mt][0], ah[mt][1], ah[mt][2], ah[mt][3], bh2, bh3);
                    MMA16816(acc[mt][2 * ng + 1], ah[mt][0], ah[mt][1], ah[mt][2], ah[mt][3], bl2, bl3);
                    MMA16816(acc[mt][2 * ng + 1], al[mt][0], al[mt][1], al[mt][2], al[mt][3], bh2, bh3);
                }
            }
        }
    }
    // drain the trailing prefetch
    asm volatile("cp.async.wait_group 0;" ::: "memory");

    // epilogue: y=0 -> fp32 C (+bias); y=1 -> fp16 Chalf
    const bool tohalf = (Chalf != nullptr) && (blockIdx.y == 1);
#pragma unroll
    for (int mt = 0; mt < 2; mt++) {
        int row0 = m0 + mw + mt * 16 + (lane >> 2);
#pragma unroll
        for (int nt = 0; nt < 8; nt++) {
            int col = nw + nt * 8 + (lane & 3) * 2;
            if (tohalf) {
                if (row0 < Mrows)
                    *(__half2*)&Chalf[(size_t)row0 * HID + col] =
                        __floats2half2_rn(acc[mt][nt][0], acc[mt][nt][1]);
                if (row0 + 8 < Mrows)
                    *(__half2*)&Chalf[(size_t)(row0 + 8) * HID + col] =
                        __floats2half2_rn(acc[mt][nt][2], acc[mt][nt][3]);
            } else {
                float b0 = bias ? bias[col] : 0.f;
                float b1 = bias ? bias[col + 1] : 0.f;
                if (row0 < Mrows)
                    *(float2*)&C[(size_t)row0 * HID + col] =
                        make_float2(acc[mt][nt][0] + b0, acc[mt][nt][1] + b1);
                if (row0 + 8 < Mrows)
                    *(float2*)&C[(size_t)(row0 + 8) * HID + col] =
                        make_float2(acc[mt][nt][2] + b0, acc[mt][nt][3] + b1);
            }
        }
    }

    // fused edge scatter: this CTA's slice of the edge list -> dst buckets
    if (edgesPerBlk > 0) {
        int bflat = blockIdx.y * gridDim.x + blockIdx.x;
        int base = bflat * edgesPerBlk;
        int end = base + edgesPerBlk;
        if (end > E) end = E;
        for (int i = base + tid; i < end; i += 256) {
            int dn = edst[i];
            int pos = atomicAdd(&g_cnt[dn], 1);
            if (pos < DCAP) {
                float wv = ew[i];
                __half2 h2 = __floats2half2_rn(wv, wv);
                g_epk[(size_t)dn * DCAP + pos] =
                    make_uint2((unsigned)esrc[i], *(unsigned*)&h2);
            }
        }
    }
}

// ---------------------------------------------------------------------------
extern "C" void kernel_launch(void* const* d_in, const int* in_sizes, int n_in,
                              void* d_out, int out_size)
{
    const float* z   = (const float*)d_in[0];
    const float* w   = (const float*)d_in[1];
    const int*   src = (const int*)  d_in[2];
    const int*   dst = (const int*)  d_in[3];
    const float* Wm  = (const float*)d_in[4];
    const float* bm  = (const float*)d_in[5];
    const float* Wu  = (const float*)d_in[6];
    const float* bu  = (const float*)d_in[7];
    float* out = (float*)d_out;

    int n = in_sizes[0] / HID;
    int E = in_sizes[1];
    if (n > MAXN) n = MAXN;
    if (E > MAXE) E = MAXE;

    float* A  = nullptr;
    __half* Bh = nullptr;
    float* M  = nullptr;
    unsigned char* Bm = nullptr;
    unsigned char* Bu = nullptr;
    cudaGetSymbolAddress((void**)&A,  g_A);
    cudaGetSymbolAddress((void**)&Bh, g_Bh);
    cudaGetSymbolAddress((void**)&M,  g_M);
    cudaGetSymbolAddress((void**)&Bm, g_Bm);
    cudaGetSymbolAddress((void**)&Bu, g_Bu);

    cudaFuncSetAttribute(mma_gemm, cudaFuncAttributeMaxDynamicSharedMemorySize, MG_SMEM);

    int nb = (n + 255) / 256;
    int gtiles = (n + 127) / 128;

    // #1: zero counts + pack both weight images
    prep<<<nb, 256>>>(Wm, Wu, n);

    // #2: [A | Bh] = z @ Wm[0:256]  (y=0 -> fp32 A, y=1 -> fp16 Bh)
    //     + fused edge scatter across all CTAs (depends only on prep)
    {
        dim3 grid(gtiles, 2);
        int nblk = gtiles * 2;
        int epb = (E + nblk - 1) / nblk;
        mma_gemm<<<grid, 256, MG_SMEM>>>(z, nullptr, Bm, nullptr, A, Bh, n, 1,
                                         src, dst, w, E, epb);
    }

    // #3: m via warp-per-node pipelined half2 register max (fused +A+bm)
    {
        const float* r = Wm + (size_t)256 * 128;
        node_max<<<(n + 7) / 8, 256>>>(r, bm, n);
    }

    // #4: h = concat(z, m) @ Wu + bu   (K=256 -> 4 subchunks)
    {
        dim3 grid(gtiles, 1);
        mma_gemm<<<grid, 256, MG_SMEM>>>(z, M, Bu, bu, out, nullptr, n, 2,
                                         nullptr, nullptr, nullptr, 0, 0);
    }
}

// round 13
// speedup vs baseline: 1.1229x; 1.1229x over previous
#include <cuda_runtime.h>
#include <cuda_bf16.h>
#include <cuda_fp16.h>
#include <cstdint>
#include <cstddef>

#define HID   128
#define MAXN  50000
#define MAXE  800000
#define DCAP  96
#define NT    391          // (MAXN+127)/128 tiles

// ---------------- scratch (device globals: allocation-free rule) ------------
__device__ __align__(16) float  g_A [(size_t)MAXN * HID];   // A = z@Wm_top (fp32)
__device__ __align__(16) __half g_Bh[(size_t)MAXN * HID];   // B = z@Wm_mid (fp16)
__device__ __align__(16) uint2  g_epk[(size_t)MAXN * DCAP]; // bucket: (src, w as half2)
__device__ int g_cnt[MAXN];
// pre-split, pre-swizzled bf16 operand images, 32KB per (tile,ksub) = [hi16K|lo16K]
__device__ __align__(1024) unsigned char g_zimg[(size_t)NT * 2 * 32768]; // A: z
__device__ __align__(1024) unsigned char g_mimg[(size_t)NT * 2 * 32768]; // A: m
__device__ __align__(1024) unsigned char g_Bm[4 * 32768]; // GEMM1 B: img=nblk*2+ksub
__device__ __align__(1024) unsigned char g_Bu[4 * 32768]; // GEMM2 B: img=ksub

// ---------------- helpers ----------------------------------------------------
__device__ __forceinline__ uint32_t s2u(const void* p) {
    uint32_t a;
    asm("{ .reg .u64 t; cvta.to.shared.u64 t, %1; cvt.u32.u64 %0, t; }" : "=r"(a) : "l"(p));
    return a;
}

// byte offset in a 16KB [128 rows][64 bf16] tile, XOR-swizzled at 16B grain
__device__ __forceinline__ uint32_t o64(int row, int kc) {
    return ((uint32_t)row << 7) + (((uint32_t)(kc ^ (row & 7))) << 4);
}

#define LDMX4(r0, r1, r2, r3, a) \
    asm volatile("ldmatrix.sync.aligned.m8n8.x4.shared.b16 {%0,%1,%2,%3}, [%4];" \
        : "=r"(r0), "=r"(r1), "=r"(r2), "=r"(r3) : "r"(a))

#define MMA16816(d, a0, a1, a2, a3, b0, b1) \
    asm volatile("mma.sync.aligned.m16n8k16.row.col.f32.bf16.bf16.f32 " \
        "{%0,%1,%2,%3}, {%4,%5,%6,%7}, {%8,%9}, {%0,%1,%2,%3};" \
        : "+f"((d)[0]), "+f"((d)[1]), "+f"((d)[2]), "+f"((d)[3]) \
        : "r"(a0), "r"(a1), "r"(a2), "r"(a3), "r"(b0), "r"(b1))

#define CPASYNC16(dst, src) \
    asm volatile("cp.async.cg.shared.global [%0], [%1], 16;" :: "r"(dst), "l"(src))

// split a float4 into packed bf16-hi / bf16-lo uint2 pairs
__device__ __forceinline__ void split4(float4 v, uint2& ph, uint2& pl) {
    __nv_bfloat16 h0 = __float2bfloat16(v.x), h1 = __float2bfloat16(v.y);
    __nv_bfloat16 h2 = __float2bfloat16(v.z), h3 = __float2bfloat16(v.w);
    __nv_bfloat16 l0 = __float2bfloat16(v.x - __bfloat162float(h0));
    __nv_bfloat16 l1 = __float2bfloat16(v.y - __bfloat162float(h1));
    __nv_bfloat16 l2 = __float2bfloat16(v.z - __bfloat162float(h2));
    __nv_bfloat16 l3 = __float2bfloat16(v.w - __bfloat162float(h3));
    ph = make_uint2(((uint32_t)__bfloat16_as_ushort(h1) << 16) | __bfloat16_as_ushort(h0),
                    ((uint32_t)__bfloat16_as_ushort(h3) << 16) | __bfloat16_as_ushort(h2));
    pl = make_uint2(((uint32_t)__bfloat16_as_ushort(l1) << 16) | __bfloat16_as_ushort(l0),
                    ((uint32_t)__bfloat16_as_ushort(l3) << 16) | __bfloat16_as_ushort(l2));
}

// ---------------- prep: zero counts + pack both B operand images --------------
__global__ void prep(const float* __restrict__ Wm, const float* __restrict__ Wu, int n) {
    int i = blockIdx.x * blockDim.x + threadIdx.x;
    if (i < 32768) {
        { // Bm: img=(n>>7)*2+(k>>6): B[n&127][k&63] = W_eff[k][n]
            int nn = i & 255, k = i >> 8;
            float v = (nn < 128) ? Wm[k * 128 + nn] : Wm[(128 + k) * 128 + (nn - 128)];
            __nv_bfloat16 h = __float2bfloat16(v);
            __nv_bfloat16 l = __float2bfloat16(v - __bfloat162float(h));
            int kk = k & 63;
            uint32_t o = (uint32_t)((nn >> 7) * 2 + (k >> 6)) * 32768
                       + o64(nn & 127, kk >> 3) + (kk & 7) * 2;
            *(__nv_bfloat16*)(g_Bm + o)         = h;
            *(__nv_bfloat16*)(g_Bm + o + 16384) = l;
        }
        { // Bu: img=(k>>6): B[n][k&63] = Wu[k][n]
            int nn = i & 127, k = i >> 7;
            float v = Wu[k * 128 + nn];
            __nv_bfloat16 h = __float2bfloat16(v);
            __nv_bfloat16 l = __float2bfloat16(v - __bfloat162float(h));
            int kk = k & 63;
            uint32_t o = (uint32_t)(k >> 6) * 32768 + o64(nn, kk >> 3) + (kk & 7) * 2;
            *(__nv_bfloat16*)(g_Bu + o)         = h;
            *(__nv_bfloat16*)(g_Bu + o + 16384) = l;
        }
    }
    if (i < n) g_cnt[i] = 0;
}

// ---------------- prep_z: split z into pre-swizzled hi/lo tile images ---------
// block b = tile t * 2 + ksub s. Thread: row r = tid>>1, k-half kh = (tid&1)*32.
__global__ __launch_bounds__(256) void prep_z(const float* __restrict__ z, int n) {
    int tid = threadIdx.x;
    int t = blockIdx.x >> 1, s = blockIdx.x & 1;
    int r = tid >> 1, kh = (tid & 1) * 32;
    int g = t * 128 + r;
    unsigned char* img = g_zimg + (size_t)blockIdx.x * 32768;
    const float* rowp = &z[(size_t)g * 128 + s * 64 + kh];
#pragma unroll
    for (int i = 0; i < 8; i++) {
        int kk = kh + i * 4;
        float4 v = make_float4(0.f, 0.f, 0.f, 0.f);
        if (g < n) v = *(const float4*)(rowp + i * 4);
        uint2 ph, pl;
        split4(v, ph, pl);
        uint32_t o = o64(r, kk >> 3) + (kk & 7) * 2;
        *(uint2*)(img + o)         = ph;
        *(uint2*)(img + 16384 + o) = pl;
    }
}

// ---------------- bucket scatter: 2 edges/thread (standalone) -----------------
__global__ void scatter_edges(const int* __restrict__ src, const int* __restrict__ dst,
                              const float* __restrict__ w, int E) {
    int i2 = (blockIdx.x * blockDim.x + threadIdx.x) * 2;
    if (i2 >= E) return;
    if (i2 + 2 <= E) {
        int2   s2 = *(const int2*)&src[i2];
        int2   d2 = *(const int2*)&dst[i2];
        float2 w2 = *(const float2*)&w[i2];
        int p0 = atomicAdd(&g_cnt[d2.x], 1);
        int p1 = atomicAdd(&g_cnt[d2.y], 1);
        if (p0 < DCAP) {
            __half2 h2 = __floats2half2_rn(w2.x, w2.x);
            g_epk[(size_t)d2.x * DCAP + p0] = make_uint2((unsigned)s2.x, *(unsigned*)&h2);
        }
        if (p1 < DCAP) {
            __half2 h2 = __floats2half2_rn(w2.y, w2.y);
            g_epk[(size_t)d2.y * DCAP + p1] = make_uint2((unsigned)s2.y, *(unsigned*)&h2);
        }
    } else {
        int d = dst[i2];
        int pos = atomicAdd(&g_cnt[d], 1);
        if (pos < DCAP) {
            __half2 h2 = __floats2half2_rn(w[i2], w[i2]);
            g_epk[(size_t)d * DCAP + pos] = make_uint2((unsigned)src[i2], *(unsigned*)&h2);
        }
    }
}

// ---------------- node_max: pipelined half2 max; writes split m images --------
//   m[d] = deg ? f32(max2_e(Bh[src_e] + w_e*r_h)) + A[d] + bm : 0
__global__ __launch_bounds__(256, 6) void node_max(const float* __restrict__ r,
                                                   const float* __restrict__ bm, int n)
{
    int warp = (blockIdx.x * blockDim.x + threadIdx.x) >> 5;
    int lane = threadIdx.x & 31;
    if (warp >= n) return;
    const int d = warp;
    const int c4 = lane * 4;

    float4 rvf = *(const float4*)&r[c4];
    const __half2 rv0 = __floats2half2_rn(rvf.x, rvf.y);
    const __half2 rv1 = __floats2half2_rn(rvf.z, rvf.w);

    int deg = g_cnt[d];
    if (deg > DCAP) deg = DCAP;
    const uint2* pay = &g_epk[(size_t)d * DCAP];
    const __half* Bbase = g_Bh + c4;

    float4 acc;
    if (deg > 0) {
        const __half2 NEGI = __half2half2(__ushort_as_half(0xFC00));
        __half2 a0 = NEGI, a1 = NEGI;
        const int dm1 = deg - 1;

        uint2 pc[4];
#pragma unroll
        for (int j = 0; j < 4; j++) pc[j] = pay[j < dm1 ? j : dm1];

        for (int e = 0; e < deg; e += 4) {
            const int rem = deg - e;
            uint2 b[4];
#pragma unroll
            for (int j = 0; j < 4; j++)
                b[j] = *(const uint2*)(Bbase + (size_t)pc[j].x * HID);
            uint2 pn[4];
#pragma unroll
            for (int j = 0; j < 4; j++) {
                int idx = e + 4 + j;
                pn[j] = pay[idx < dm1 ? idx : dm1];
            }
#pragma unroll
            for (int j = 0; j < 4; j++) {
                if (j < rem) {
                    __half2 ww = *(__half2*)&pc[j].y;
                    a0 = __hmax2(a0, __hfma2(ww, rv0, *(__half2*)&b[j].x));
                    a1 = __hmax2(a1, __hfma2(ww, rv1, *(__half2*)&b[j].y));
                }
            }
#pragma unroll
            for (int j = 0; j < 4; j++) pc[j] = pn[j];
        }
        float2 f0 = __half22float2(a0);
        float2 f1 = __half22float2(a1);
        float4 a   = *(const float4*)&g_A[(size_t)d * HID + c4];
        float4 bmv = *(const float4*)&bm[c4];
        acc = make_float4(f0.x + a.x + bmv.x, f0.y + a.y + bmv.y,
                          f1.x + a.z + bmv.z, f1.y + a.w + bmv.w);
    } else {
        acc = make_float4(0.f, 0.f, 0.f, 0.f);
    }
    // write m directly as split, pre-swizzled bf16 image (GEMM2 operand)
    {
        int t = d >> 7, rr = d & 127;
        int kk = c4 & 63;
        unsigned char* img = g_mimg + (size_t)(t * 2 + (c4 >> 6)) * 32768;
        uint2 ph, pl;
        split4(acc, ph, pl);
        uint32_t o = o64(rr, kk >> 3) + (kk & 7) * 2;
        *(uint2*)(img + o)         = ph;
        *(uint2*)(img + 16384 + o) = pl;
    }
}

// ---------------- split-bf16 HMMA GEMM, all-cp.async operands -----------------
// smem: A buf0 32K | A buf1 32K | B 32K = 96KB (2 CTA/SM)
// A: per-tile pre-split images (gk<2 -> A0img, gk>=2 -> A1img), double-buffered.
// B: weight images, single-buffered (L2-hot).
// y=0 tile -> fp32 C (+bias); y=1 tile (GEMM1 only) -> fp16 Chalf, no bias.
// acc = Ah*Bh + Ah*Bl + Al*Bh  (split-bf16, ~2^-16 rel err)
#define SM_B 65536
#define MG_SMEM 98304

__global__ __launch_bounds__(256, 2) void mma_gemm(
    const unsigned char* __restrict__ A0img, const unsigned char* __restrict__ A1img,
    const unsigned char* __restrict__ Bimg, const float* __restrict__ bias,
    float* __restrict__ C, __half* __restrict__ Chalf, int Mrows, int Kchunks)
{
    extern __shared__ __align__(1024) unsigned char sm[];
    const uint32_t sb = s2u(sm);
    const int tid = threadIdx.x, w = tid >> 5, lane = tid & 31;
    const int m0 = blockIdx.x * 128;
    const int totalKsubs = Kchunks * 2;

    float acc[2][8][4];
#pragma unroll
    for (int i = 0; i < 2; i++)
#pragma unroll
        for (int j = 0; j < 8; j++)
#pragma unroll
            for (int q = 0; q < 4; q++) acc[i][j][q] = 0.f;

    const int mw = (w & 3) * 32;      // warp M offset in tile
    const int nw = (w >> 2) * 64;     // warp N offset in tile

    // A image source for subchunk gk
    auto asrc = [&](int gk) -> const unsigned char* {
        const unsigned char* im = (gk >> 1) ? A1img : A0img;
        return im + (size_t)(blockIdx.x * 2 + (gk & 1)) * 32768;
    };

    // prefetch A(0) into buf0
    {
        const unsigned char* s = asrc(0) + tid * 16;
        uint32_t dstA = sb + tid * 16;
#pragma unroll
        for (int i = 0; i < 8; i++) CPASYNC16(dstA + i * 4096, s + i * 4096);
        asm volatile("cp.async.commit_group;");
    }

    for (int gk = 0; gk < totalKsubs; ++gk) {
        if (gk) __syncthreads();   // prev compute done; B buf + other A buf free

        // B(gk) -> single B buffer
        {
            const unsigned char* s = Bimg +
                (size_t)(blockIdx.y * totalKsubs + gk) * 32768 + tid * 16;
            uint32_t dstB = sb + SM_B + tid * 16;
#pragma unroll
            for (int i = 0; i < 8; i++) CPASYNC16(dstB + i * 4096, s + i * 4096);
            asm volatile("cp.async.commit_group;");
        }
        // A(gk+1) -> other A buffer (skip past end; commit empty group to keep count)
        {
            if (gk + 1 < totalKsubs) {
                const unsigned char* s = asrc(gk + 1) + tid * 16;
                uint32_t dstA = sb + ((gk + 1) & 1) * 32768 + tid * 16;
#pragma unroll
                for (int i = 0; i < 8; i++) CPASYNC16(dstA + i * 4096, s + i * 4096);
            }
            asm volatile("cp.async.commit_group;");
        }
        // wait: A(gk) + B(gk) done, A(gk+1) may stay in flight
        asm volatile("cp.async.wait_group 1;" ::: "memory");
        __syncthreads();

        const uint32_t sbA = sb + (gk & 1) * 32768;   // [hi 16K | lo 16K]
        const uint32_t sbB = sb + SM_B;

        // compute: 4 k16 steps over this 64-k subchunk
#pragma unroll
        for (int ks = 0; ks < 4; ++ks) {
            const int kc = ks * 2;
            uint32_t ah[2][4], al[2][4];
#pragma unroll
            for (int mt = 0; mt < 2; mt++) {
                int row = mw + mt * 16 + (lane & 15);
                uint32_t off = o64(row, kc + (lane >> 4));
                LDMX4(ah[mt][0], ah[mt][1], ah[mt][2], ah[mt][3], sbA + off);
                LDMX4(al[mt][0], al[mt][1], al[mt][2], al[mt][3], sbA + 16384 + off);
            }
#pragma unroll
            for (int ng = 0; ng < 4; ng++) {
                int rowb = nw + ng * 16 + (lane & 7) + ((lane >> 4) << 3);
                uint32_t offb = o64(rowb, kc + ((lane >> 3) & 1));
                uint32_t bh0, bh1, bh2, bh3, bl0, bl1, bl2, bl3;
                LDMX4(bh0, bh1, bh2, bh3, sbB + offb);
                LDMX4(bl0, bl1, bl2, bl3, sbB + 16384 + offb);
#pragma unroll
                for (int mt = 0; mt < 2; mt++) {
                    MMA16816(acc[mt][2 * ng],     ah[mt][0], ah[mt][1], ah[mt][2], ah[mt][3], bh0, bh1);
                    MMA16816(acc[mt][2 * ng],     ah[mt][0], ah[mt][1], ah[mt][2], ah[mt][3], bl0, bl1);
                    MMA16816(acc[mt][2 * ng],     al[mt][0], al[mt][1], al[mt][2], al[mt][3], bh0, bh1);
                    MMA16816(acc[mt][2 * ng + 1], ah[mt][0], ah[mt][1], ah[mt][2], ah[mt][3], bh2, bh3);
                    MMA16816(acc[mt][2 * ng + 1], ah[mt][0], ah[mt][1], ah[mt][2], ah[mt][3], bl2, bl3);
                    MMA16816(acc[mt][2 * ng + 1], al[mt][0], al[mt][1], al[mt][2], al[mt][3], bh2, bh3);
                }
            }
        }
    }
    asm volatile("cp.async.wait_group 0;" ::: "memory");

    // epilogue: y=0 -> fp32 C (+bias); y=1 -> fp16 Chalf
    const bool tohalf = (Chalf != nullptr) && (blockIdx.y == 1);
#pragma unroll
    for (int mt = 0; mt < 2; mt++) {
        int row0 = m0 + mw + mt * 16 + (lane >> 2);
#pragma unroll
        for (int nt = 0; nt < 8; nt++) {
            int col = nw + nt * 8 + (lane & 3) * 2;
            if (tohalf) {
                if (row0 < Mrows)
                    *(__half2*)&Chalf[(size_t)row0 * HID + col] =
                        __floats2half2_rn(acc[mt][nt][0], acc[mt][nt][1]);
                if (row0 + 8 < Mrows)
                    *(__half2*)&Chalf[(size_t)(row0 + 8) * HID + col] =
                        __floats2half2_rn(acc[mt][nt][2], acc[mt][nt][3]);
            } else {
                float b0 = bias ? bias[col] : 0.f;
                float b1 = bias ? bias[col + 1] : 0.f;
                if (row0 < Mrows)
                    *(float2*)&C[(size_t)row0 * HID + col] =
                        make_float2(acc[mt][nt][0] + b0, acc[mt][nt][1] + b1);
                if (row0 + 8 < Mrows)
                    *(float2*)&C[(size_t)(row0 + 8) * HID + col] =
                        make_float2(acc[mt][nt][2] + b0, acc[mt][nt][3] + b1);
            }
        }
    }
}

// ---------------------------------------------------------------------------
extern "C" void kernel_launch(void* const* d_in, const int* in_sizes, int n_in,
                              void* d_out, int out_size)
{
    const float* z   = (const float*)d_in[0];
    const float* w   = (const float*)d_in[1];
    const int*   src = (const int*)  d_in[2];
    const int*   dst = (const int*)  d_in[3];
    const float* Wm  = (const float*)d_in[4];
    const float* bm  = (const float*)d_in[5];
    const float* Wu  = (const float*)d_in[6];
    const float* bu  = (const float*)d_in[7];
    float* out = (float*)d_out;

    int n = in_sizes[0] / HID;
    int E = in_sizes[1];
    if (n > MAXN) n = MAXN;
    if (E > MAXE) E = MAXE;

    float* A  = nullptr;
    __half* Bh = nullptr;
    unsigned char *Bm = nullptr, *Bu = nullptr, *zimg = nullptr, *mimg = nullptr;
    cudaGetSymbolAddress((void**)&A,    g_A);
    cudaGetSymbolAddress((void**)&Bh,   g_Bh);
    cudaGetSymbolAddress((void**)&Bm,   g_Bm);
    cudaGetSymbolAddress((void**)&Bu,   g_Bu);
    cudaGetSymbolAddress((void**)&zimg, g_zimg);
    cudaGetSymbolAddress((void**)&mimg, g_mimg);

    cudaFuncSetAttribute(mma_gemm, cudaFuncAttributeMaxDynamicSharedMemorySize, MG_SMEM);

    int nb = (n + 255) / 256;
    int gtiles = (n + 127) / 128;

    // #1: zero counts + pack both weight images
    prep<<<nb, 256>>>(Wm, Wu, n);

    // #2: split z into pre-swizzled per-tile images
    prep_z<<<gtiles * 2, 256>>>(z, n);

    // #3: [A | Bh] = z @ Wm[0:256]  (y=0 -> fp32 A, y=1 -> fp16 Bh)
    {
        dim3 grid(gtiles, 2);
        mma_gemm<<<grid, 256, MG_SMEM>>>(zimg, zimg, Bm, nullptr, A, Bh, n, 1);
    }

    // #4: bucket scatter (standalone)
    scatter_edges<<<(E + 511) / 512, 256>>>(src, dst, w, E);

    // #5: m via pipelined half2 register max; writes split m images
    {
        const float* r = Wm + (size_t)256 * 128;
        node_max<<<(n + 7) / 8, 256>>>(r, bm, n);
    }

    // #6: h = concat(z, m) @ Wu + bu   (gk 0,1 from zimg; gk 2,3 from mimg)
    {
        dim3 grid(gtiles, 1);
        mma_gemm<<<grid, 256, MG_SMEM>>>(zimg, mimg, Bu, bu, out, nullptr, n, 2);
    }
}